// round 2
// baseline (speedup 1.0000x reference)
#include <cuda_runtime.h>
#include <math_constants.h>

#define NTOK 8192
#define EDIM 768
#define E3   2304
#define HD   64
#define ATTN_SCALE 0.125f

__device__ float g_qkv[NTOK * E3];
__device__ float g_o[NTOK * EDIM];
__device__ float g_on[NTOK * EDIM];

// ---------------------------------------------------------------------------
// SGEMM core: C[M,N] = A @ B^T + bias (row-major NT), 128x128x16 tile,
// 256 threads, 8x8 microtile. MODE 0: A=x (param), C=g_qkv. MODE 1: A=g_on,
// C=param. Template keeps device-global refs inside device code.
// ---------------------------------------------------------------------------
template <int MODE>
__global__ __launch_bounds__(256, 2) void sgemm_nt_bias(
    const float* __restrict__ Ain, const float* __restrict__ B,
    const float* __restrict__ bias, float* __restrict__ Cout,
    int N, int K)
{
    const float* A = (MODE == 0) ? Ain : g_on;
    float* C = (MODE == 0) ? g_qkv : Cout;

    __shared__ float As[16][128];
    __shared__ float Bs[16][128];
    const int tid = threadIdx.x;
    const int tx = tid & 15;
    const int ty = tid >> 4;
    const int rowBase = blockIdx.y << 7;
    const int colBase = blockIdx.x << 7;
    const int lr = tid >> 2;
    const int lk = (tid & 3) << 2;

    const float* Ap = A + (size_t)(rowBase + lr) * K + lk;
    const float* Bp = B + (size_t)(colBase + lr) * K + lk;
    const size_t stride64 = (size_t)64 * K;

    float acc[8][8];
#pragma unroll
    for (int i = 0; i < 8; ++i)
#pragma unroll
        for (int j = 0; j < 8; ++j) acc[i][j] = 0.f;

    for (int k0 = 0; k0 < K; k0 += 16) {
        float4 a0 = *(const float4*)(Ap + k0);
        float4 a1 = *(const float4*)(Ap + stride64 + k0);
        float4 b0 = *(const float4*)(Bp + k0);
        float4 b1 = *(const float4*)(Bp + stride64 + k0);
        __syncthreads();
        As[lk+0][lr] = a0.x; As[lk+1][lr] = a0.y; As[lk+2][lr] = a0.z; As[lk+3][lr] = a0.w;
        As[lk+0][lr+64] = a1.x; As[lk+1][lr+64] = a1.y; As[lk+2][lr+64] = a1.z; As[lk+3][lr+64] = a1.w;
        Bs[lk+0][lr] = b0.x; Bs[lk+1][lr] = b0.y; Bs[lk+2][lr] = b0.z; Bs[lk+3][lr] = b0.w;
        Bs[lk+0][lr+64] = b1.x; Bs[lk+1][lr+64] = b1.y; Bs[lk+2][lr+64] = b1.z; Bs[lk+3][lr+64] = b1.w;
        __syncthreads();
#pragma unroll
        for (int kk = 0; kk < 16; ++kk) {
            float4 av0 = *(const float4*)&As[kk][ty * 8];
            float4 av1 = *(const float4*)&As[kk][ty * 8 + 4];
            float4 bv0 = *(const float4*)&Bs[kk][tx * 8];
            float4 bv1 = *(const float4*)&Bs[kk][tx * 8 + 4];
            float a[8] = {av0.x, av0.y, av0.z, av0.w, av1.x, av1.y, av1.z, av1.w};
            float b[8] = {bv0.x, bv0.y, bv0.z, bv0.w, bv1.x, bv1.y, bv1.z, bv1.w};
#pragma unroll
            for (int i = 0; i < 8; ++i)
#pragma unroll
                for (int j = 0; j < 8; ++j) acc[i][j] = fmaf(a[i], b[j], acc[i][j]);
        }
    }

    float bb[8];
#pragma unroll
    for (int j = 0; j < 8; ++j) bb[j] = bias[colBase + tx * 8 + j];
#pragma unroll
    for (int i = 0; i < 8; ++i) {
        float* cp = C + (size_t)(rowBase + ty * 8 + i) * N + colBase + tx * 8;
        *(float4*)cp = make_float4(acc[i][0] + bb[0], acc[i][1] + bb[1],
                                   acc[i][2] + bb[2], acc[i][3] + bb[3]);
        *(float4*)(cp + 4) = make_float4(acc[i][4] + bb[4], acc[i][5] + bb[5],
                                         acc[i][6] + bb[6], acc[i][7] + bb[7]);
    }
}

// ---------------------------------------------------------------------------
// Dilated flash attention: 28 problems, each 2048q x 2048k x d64.
// ---------------------------------------------------------------------------
__global__ __launch_bounds__(256, 2) void dilated_attn()
{
    __shared__ float Qst[64][64];
    __shared__ float KPst[64][64];
    __shared__ float Vs[64][64];

    const float* __restrict__ qkv = g_qkv;

    const int p = blockIdx.y;
    int mseg, hh, grp, s, r, off;
    if (p < 16)      { grp = 0; mseg = p >> 2;        hh = p & 3;        s = 2048; r = 1; off = 0; }
    else if (p < 24) { grp = 1; mseg = (p - 16) >> 2; hh = (p - 16) & 3; s = 4096; r = 2; off = 1; }
    else             { grp = 2; mseg = 0;             hh = p - 24;       s = 8192; r = 4; off = 2; }
    const int h = grp * 4 + hh;
    const int segBase = mseg * s + off;

    const int tid = threadIdx.x;
    const int tx = tid & 15;
    const int ty = tid >> 4;
    const int lr = tid >> 2;
    const int ld = (tid & 3) << 2;

    {
        const int tok = segBase + (blockIdx.x * 64 + lr) * r;
        const float* qp = qkv + (size_t)tok * E3 + h * HD;
#pragma unroll
        for (int ii = 0; ii < 4; ++ii) {
            const int d = ld + ii * 16;
            float4 v = *(const float4*)(qp + d);
            Qst[d+0][lr] = v.x; Qst[d+1][lr] = v.y; Qst[d+2][lr] = v.z; Qst[d+3][lr] = v.w;
        }
    }

    float mreg[4], lreg[4], oacc[4][4];
#pragma unroll
    for (int i = 0; i < 4; ++i) {
        mreg[i] = -CUDART_INF_F; lreg[i] = 0.f;
#pragma unroll
        for (int j = 0; j < 4; ++j) oacc[i][j] = 0.f;
    }

    for (int kt = 0; kt < 32; ++kt) {
        __syncthreads();
        {
            const int tok = segBase + (kt * 64 + lr) * r;
            const float* kp = qkv + (size_t)tok * E3 + EDIM + h * HD;
            const float* vp = kp + EDIM;
#pragma unroll
            for (int ii = 0; ii < 4; ++ii) {
                const int d = ld + ii * 16;
                float4 kv = *(const float4*)(kp + d);
                KPst[d+0][lr] = kv.x; KPst[d+1][lr] = kv.y; KPst[d+2][lr] = kv.z; KPst[d+3][lr] = kv.w;
                *(float4*)&Vs[lr][d] = *(const float4*)(vp + d);
            }
        }
        __syncthreads();

        float sc[4][4];
#pragma unroll
        for (int i = 0; i < 4; ++i)
#pragma unroll
            for (int j = 0; j < 4; ++j) sc[i][j] = 0.f;
#pragma unroll 8
        for (int d = 0; d < 64; ++d) {
            float4 qa = *(const float4*)&Qst[d][ty * 4];
            float4 kb = *(const float4*)&KPst[d][tx * 4];
            float a[4] = {qa.x, qa.y, qa.z, qa.w};
            float b[4] = {kb.x, kb.y, kb.z, kb.w};
#pragma unroll
            for (int i = 0; i < 4; ++i)
#pragma unroll
                for (int j = 0; j < 4; ++j) sc[i][j] = fmaf(a[i], b[j], sc[i][j]);
        }
#pragma unroll
        for (int i = 0; i < 4; ++i)
#pragma unroll
            for (int j = 0; j < 4; ++j) sc[i][j] *= ATTN_SCALE;

#pragma unroll
        for (int i = 0; i < 4; ++i) {
            float tm = fmaxf(fmaxf(sc[i][0], sc[i][1]), fmaxf(sc[i][2], sc[i][3]));
#pragma unroll
            for (int w = 8; w >= 1; w >>= 1)
                tm = fmaxf(tm, __shfl_xor_sync(0xffffffffu, tm, w));
            float nm = fmaxf(mreg[i], tm);
            float corr = __expf(mreg[i] - nm);
            float rs = 0.f;
#pragma unroll
            for (int j = 0; j < 4; ++j) { sc[i][j] = __expf(sc[i][j] - nm); rs += sc[i][j]; }
#pragma unroll
            for (int w = 8; w >= 1; w >>= 1)
                rs += __shfl_xor_sync(0xffffffffu, rs, w);
            lreg[i] = lreg[i] * corr + rs;
            mreg[i] = nm;
#pragma unroll
            for (int j = 0; j < 4; ++j) oacc[i][j] *= corr;
        }

        __syncthreads();
#pragma unroll
        for (int i = 0; i < 4; ++i)
#pragma unroll
            for (int j = 0; j < 4; ++j)
                KPst[tx * 4 + j][ty * 4 + i] = sc[i][j];
        __syncthreads();

#pragma unroll 8
        for (int kk = 0; kk < 64; ++kk) {
            float4 pa = *(const float4*)&KPst[kk][ty * 4];
            float4 vb = *(const float4*)&Vs[kk][tx * 4];
            float a[4] = {pa.x, pa.y, pa.z, pa.w};
            float b[4] = {vb.x, vb.y, vb.z, vb.w};
#pragma unroll
            for (int i = 0; i < 4; ++i)
#pragma unroll
                for (int j = 0; j < 4; ++j) oacc[i][j] = fmaf(a[i], b[j], oacc[i][j]);
        }
    }

#pragma unroll
    for (int i = 0; i < 4; ++i) {
        const float inv = 1.f / lreg[i];
        const int tok = segBase + (blockIdx.x * 64 + ty * 4 + i) * r;
        *(float4*)(g_o + (size_t)tok * EDIM + h * HD + tx * 4) =
            make_float4(oacc[i][0] * inv, oacc[i][1] * inv,
                        oacc[i][2] * inv, oacc[i][3] * inv);
    }
}

// ---------------------------------------------------------------------------
__global__ __launch_bounds__(256) void layernorm_k(
    const float* __restrict__ gamma, const float* __restrict__ beta)
{
    __shared__ float red[8];
    __shared__ float bcast;
    const int row = blockIdx.x;
    const int tid = threadIdx.x;
    const int lane = tid & 31, wid = tid >> 5;
    const float* x = g_o + (size_t)row * EDIM;
    float v0 = x[tid], v1 = x[tid + 256], v2 = x[tid + 512];

    float ssum = v0 + v1 + v2;
#pragma unroll
    for (int w = 16; w >= 1; w >>= 1) ssum += __shfl_xor_sync(0xffffffffu, ssum, w);
    if (lane == 0) red[wid] = ssum;
    __syncthreads();
    if (tid < 32) {
        float t = (tid < 8) ? red[tid] : 0.f;
#pragma unroll
        for (int w = 4; w >= 1; w >>= 1) t += __shfl_xor_sync(0xffffffffu, t, w);
        if (tid == 0) bcast = t;
    }
    __syncthreads();
    const float mu = bcast * (1.f / 768.f);
    float d0 = v0 - mu, d1 = v1 - mu, d2 = v2 - mu;
    float sq = d0 * d0 + d1 * d1 + d2 * d2;
#pragma unroll
    for (int w = 16; w >= 1; w >>= 1) sq += __shfl_xor_sync(0xffffffffu, sq, w);
    __syncthreads();
    if (lane == 0) red[wid] = sq;
    __syncthreads();
    if (tid < 32) {
        float t = (tid < 8) ? red[tid] : 0.f;
#pragma unroll
        for (int w = 4; w >= 1; w >>= 1) t += __shfl_xor_sync(0xffffffffu, t, w);
        if (tid == 0) bcast = t;
    }
    __syncthreads();
    const float rstd = rsqrtf(bcast * (1.f / 768.f) + 1e-5f);
    float* y = g_on + (size_t)row * EDIM;
    y[tid]       = d0 * rstd * gamma[tid]       + beta[tid];
    y[tid + 256] = d1 * rstd * gamma[tid + 256] + beta[tid + 256];
    y[tid + 512] = d2 * rstd * gamma[tid + 512] + beta[tid + 512];
}

__global__ void zero_o() {
    ((float4*)g_o)[blockIdx.x * blockDim.x + threadIdx.x] =
        make_float4(0.f, 0.f, 0.f, 0.f);
}

// ---------------------------------------------------------------------------
extern "C" void kernel_launch(void* const* d_in, const int* in_sizes, int n_in,
                              void* d_out, int out_size)
{
    const float* x      = (const float*)d_in[0];
    const float* w_qkv  = (const float*)d_in[1];
    const float* b_qkv  = (const float*)d_in[2];
    const float* w_out  = (const float*)d_in[3];
    const float* b_out  = (const float*)d_in[4];
    const float* ln_g   = (const float*)d_in[5];
    const float* ln_b   = (const float*)d_in[6];
    float* out = (float*)d_out;

    dim3 g1(E3 / 128, NTOK / 128);
    sgemm_nt_bias<0><<<g1, 256>>>(x, w_qkv, b_qkv, nullptr, E3, EDIM);

    zero_o<<<(NTOK * EDIM / 4) / 256, 256>>>();

    dim3 g2(32, 28);
    dilated_attn<<<g2, 256>>>();

    layernorm_k<<<NTOK, 256>>>(ln_g, ln_b);

    dim3 g3(EDIM / 128, NTOK / 128);
    sgemm_nt_bias<1><<<g3, 256>>>(nullptr, w_out, b_out, out, EDIM, EDIM);
}

// round 4
// speedup vs baseline: 1.2619x; 1.2619x over previous
#include <cuda_runtime.h>
#include <cuda_bf16.h>
#include <math_constants.h>
#include <cstdint>

#define NTOK 8192
#define EDIM 768
#define E3   2304
#define HD   64
#define ATTN_SCALE 0.125f

// ---------------- scratch (device globals; allocation-free rule) -----------
__device__ float g_qkv[NTOK * E3];           // fp32 q|k|v, attention input
__device__ float g_o[NTOK * EDIM];           // attention output
__device__ __nv_bfloat16 g_xhi[NTOK * EDIM];
__device__ __nv_bfloat16 g_xlo[NTOK * EDIM];
__device__ __nv_bfloat16 g_wqhi[E3 * EDIM];
__device__ __nv_bfloat16 g_wqlo[E3 * EDIM];
__device__ __nv_bfloat16 g_wohi[EDIM * EDIM];
__device__ __nv_bfloat16 g_wolo[EDIM * EDIM];
__device__ __nv_bfloat16 g_onhi[NTOK * EDIM];
__device__ __nv_bfloat16 g_onlo[NTOK * EDIM];

// ---------------------------------------------------------------------------
// Warp-level bf16 MMA (legacy HMMA path — works on compute_103 target).
// ---------------------------------------------------------------------------
__device__ __forceinline__ void mma16816(float* c, const uint32_t* a, const uint32_t* b)
{
    asm volatile(
        "mma.sync.aligned.m16n8k16.row.col.f32.bf16.bf16.f32 "
        "{%0,%1,%2,%3}, {%4,%5,%6,%7}, {%8,%9}, {%0,%1,%2,%3};"
        : "+f"(c[0]), "+f"(c[1]), "+f"(c[2]), "+f"(c[3])
        : "r"(a[0]), "r"(a[1]), "r"(a[2]), "r"(a[3]), "r"(b[0]), "r"(b[1]));
}

// ---------------------------------------------------------------------------
// Split-bf16 tensor-core GEMM: C[8192,NTOT] = A[8192,768] @ B[NTOT,768]^T + bias
// A≈Ahi+Alo, B≈Bhi+Blo;  C = AhiBhi + AhiBlo + AloBhi  (fp32 accum).
// Block 128x128, 8 warps x (64x32), K-chunk 32, double-buffered smem.
// Smem tile: 128 rows x 40 bf16 (pad 8 -> conflict-free frag loads), 10240 B.
// Layout: stage s in {0,1}, tile t in {Ahi,Alo,Bhi,Blo}: offset (s*4+t)*10240.
// MODE 0: A=g_x*,  B=g_wq*, C=g_qkv (NTOT=2304)
// MODE 1: A=g_on*, B=g_wo*, C=Cout  (NTOT=768)
// ---------------------------------------------------------------------------
#define TILE_B 10240
#define STG_B  40960

template <int MODE>
__global__ __launch_bounds__(256) void wgemm(const float* __restrict__ bias,
                                             float* __restrict__ Cout)
{
    constexpr int NTOT = (MODE == 0) ? E3 : EDIM;
    constexpr int NC = 24;                 // 768 / 32
    extern __shared__ char smem[];

    const int tid = threadIdx.x;
    const int lane = tid & 31;
    const int wid = tid >> 5;
    const int rowBase = blockIdx.y << 7;
    const int colBase = blockIdx.x << 7;
    const int mBase = (wid & 1) * 64;      // warp row offset in tile
    const int nBase = (wid >> 1) * 32;     // warp col offset in tile

    const __nv_bfloat16* Ahi = (MODE == 0) ? g_xhi : g_onhi;
    const __nv_bfloat16* Alo = (MODE == 0) ? g_xlo : g_onlo;
    const __nv_bfloat16* Bhi = (MODE == 0) ? g_wqhi : g_wohi;
    const __nv_bfloat16* Blo = (MODE == 0) ? g_wqlo : g_wolo;
    float* C = (MODE == 0) ? g_qkv : Cout;

    // global-load assignment: thread -> (row = tid>>1, 16-elem half = tid&1)
    const int lr = tid >> 1;
    const int lh = tid & 1;
    const __nv_bfloat16* gA0 = Ahi + (size_t)(rowBase + lr) * EDIM + lh * 16;
    const __nv_bfloat16* gA1 = Alo + (size_t)(rowBase + lr) * EDIM + lh * 16;
    const __nv_bfloat16* gB0 = Bhi + (size_t)(colBase + lr) * EDIM + lh * 16;
    const __nv_bfloat16* gB1 = Blo + (size_t)(colBase + lr) * EDIM + lh * 16;
    const uint32_t soff = (uint32_t)(lr * 80 + lh * 32);   // bytes into a tile

    float acc[4][4][4];
#pragma unroll
    for (int mi = 0; mi < 4; ++mi)
#pragma unroll
        for (int ni = 0; ni < 4; ++ni)
#pragma unroll
            for (int r = 0; r < 4; ++r) acc[mi][ni][r] = 0.f;

    // preload chunk 0 into stage 0
    {
        char* st = smem;
        *(uint4*)(st + 0 * TILE_B + soff)      = *(const uint4*)(gA0);
        *(uint4*)(st + 0 * TILE_B + soff + 16) = *(const uint4*)(gA0 + 8);
        *(uint4*)(st + 1 * TILE_B + soff)      = *(const uint4*)(gA1);
        *(uint4*)(st + 1 * TILE_B + soff + 16) = *(const uint4*)(gA1 + 8);
        *(uint4*)(st + 2 * TILE_B + soff)      = *(const uint4*)(gB0);
        *(uint4*)(st + 2 * TILE_B + soff + 16) = *(const uint4*)(gB0 + 8);
        *(uint4*)(st + 3 * TILE_B + soff)      = *(const uint4*)(gB1);
        *(uint4*)(st + 3 * TILE_B + soff + 16) = *(const uint4*)(gB1 + 8);
    }
    __syncthreads();

    const int g = lane >> 2;     // group id 0..7
    const int q = lane & 3;      // quad lane

    for (int c = 0; c < NC; ++c) {
        const int stg = c & 1;

        // issue next chunk's global loads into registers
        uint4 ra[8];
        if (c + 1 < NC) {
            const int off = (c + 1) * 32;
            ra[0] = *(const uint4*)(gA0 + off); ra[1] = *(const uint4*)(gA0 + off + 8);
            ra[2] = *(const uint4*)(gA1 + off); ra[3] = *(const uint4*)(gA1 + off + 8);
            ra[4] = *(const uint4*)(gB0 + off); ra[5] = *(const uint4*)(gB0 + off + 8);
            ra[6] = *(const uint4*)(gB1 + off); ra[7] = *(const uint4*)(gB1 + off + 8);
        }

        // compute on current stage
        const char* As = smem + stg * STG_B;
        const char* Al = As + TILE_B;
        const char* Bh = As + 2 * TILE_B;
        const char* Bl = As + 3 * TILE_B;
#pragma unroll
        for (int k0 = 0; k0 < 32; k0 += 16) {
            uint32_t ahi[4][4], alo[4][4];
#pragma unroll
            for (int mi = 0; mi < 4; ++mi)
#pragma unroll
                for (int r = 0; r < 4; ++r) {
                    const int row = mBase + mi * 16 + g + 8 * (r & 1);
                    const int col = k0 + q * 2 + 8 * (r >> 1);
                    ahi[mi][r] = *(const uint32_t*)(As + row * 80 + col * 2);
                    alo[mi][r] = *(const uint32_t*)(Al + row * 80 + col * 2);
                }
            uint32_t bhi[4][2], blo[4][2];
#pragma unroll
            for (int ni = 0; ni < 4; ++ni)
#pragma unroll
                for (int r = 0; r < 2; ++r) {
                    const int nr = nBase + ni * 8 + g;
                    const int col = k0 + q * 2 + 8 * r;
                    bhi[ni][r] = *(const uint32_t*)(Bh + nr * 80 + col * 2);
                    blo[ni][r] = *(const uint32_t*)(Bl + nr * 80 + col * 2);
                }
#pragma unroll
            for (int mi = 0; mi < 4; ++mi)
#pragma unroll
                for (int ni = 0; ni < 4; ++ni) {
                    mma16816(acc[mi][ni], ahi[mi], bhi[ni]);
                    mma16816(acc[mi][ni], ahi[mi], blo[ni]);
                    mma16816(acc[mi][ni], alo[mi], bhi[ni]);
                }
        }

        // store next chunk into the other stage (safe: not being read)
        if (c + 1 < NC) {
            char* st = smem + ((c + 1) & 1) * STG_B;
            *(uint4*)(st + 0 * TILE_B + soff)      = ra[0];
            *(uint4*)(st + 0 * TILE_B + soff + 16) = ra[1];
            *(uint4*)(st + 1 * TILE_B + soff)      = ra[2];
            *(uint4*)(st + 1 * TILE_B + soff + 16) = ra[3];
            *(uint4*)(st + 2 * TILE_B + soff)      = ra[4];
            *(uint4*)(st + 2 * TILE_B + soff + 16) = ra[5];
            *(uint4*)(st + 3 * TILE_B + soff)      = ra[6];
            *(uint4*)(st + 3 * TILE_B + soff + 16) = ra[7];
        }
        __syncthreads();
    }

    // epilogue: bias add + store fp32
#pragma unroll
    for (int mi = 0; mi < 4; ++mi) {
        const int row0 = rowBase + mBase + mi * 16 + g;
#pragma unroll
        for (int ni = 0; ni < 4; ++ni) {
            const int colg = colBase + nBase + ni * 8 + q * 2;
            const float b0 = bias[colg], b1 = bias[colg + 1];
            float* c0 = C + (size_t)row0 * NTOT + colg;
            float* c1 = C + (size_t)(row0 + 8) * NTOT + colg;
            c0[0] = acc[mi][ni][0] + b0; c0[1] = acc[mi][ni][1] + b1;
            c1[0] = acc[mi][ni][2] + b0; c1[1] = acc[mi][ni][3] + b1;
        }
    }
}

// ---------------------------------------------------------------------------
// fp32 -> bf16 hi/lo split. WHICH 0: x, 1: w_qkv, 2: w_out
// ---------------------------------------------------------------------------
template <int WHICH>
__global__ void split_k(const float* __restrict__ src)
{
    __nv_bfloat16* hi = (WHICH == 0) ? g_xhi : (WHICH == 1) ? g_wqhi : g_wohi;
    __nv_bfloat16* lo = (WHICH == 0) ? g_xlo : (WHICH == 1) ? g_wqlo : g_wolo;
    const int i = blockIdx.x * blockDim.x + threadIdx.x;
    float4 v = ((const float4*)src)[i];
    float a[4] = {v.x, v.y, v.z, v.w};
    const int base = i * 4;
#pragma unroll
    for (int j = 0; j < 4; ++j) {
        __nv_bfloat16 h = __float2bfloat16_rn(a[j]);
        hi[base + j] = h;
        lo[base + j] = __float2bfloat16_rn(a[j] - __bfloat162float(h));
    }
}

// ---------------------------------------------------------------------------
// Dilated flash attention (fp32 path): 28 problems, 2048q x 2048k x 64
// ---------------------------------------------------------------------------
__global__ __launch_bounds__(256, 2) void dilated_attn()
{
    __shared__ float Qst[64][64];
    __shared__ float KPst[64][64];
    __shared__ float Vs[64][64];

    const float* __restrict__ qkv = g_qkv;

    const int p = blockIdx.y;
    int mseg, hh, grp, s, r, off;
    if (p < 16)      { grp = 0; mseg = p >> 2;        hh = p & 3;        s = 2048; r = 1; off = 0; }
    else if (p < 24) { grp = 1; mseg = (p - 16) >> 2; hh = (p - 16) & 3; s = 4096; r = 2; off = 1; }
    else             { grp = 2; mseg = 0;             hh = p - 24;       s = 8192; r = 4; off = 2; }
    const int h = grp * 4 + hh;
    const int segBase = mseg * s + off;

    const int tid = threadIdx.x;
    const int tx = tid & 15;
    const int ty = tid >> 4;
    const int lr = tid >> 2;
    const int ld = (tid & 3) << 2;

    {
        const int tok = segBase + (blockIdx.x * 64 + lr) * r;
        const float* qp = qkv + (size_t)tok * E3 + h * HD;
#pragma unroll
        for (int ii = 0; ii < 4; ++ii) {
            const int d = ld + ii * 16;
            float4 v = *(const float4*)(qp + d);
            Qst[d+0][lr] = v.x; Qst[d+1][lr] = v.y; Qst[d+2][lr] = v.z; Qst[d+3][lr] = v.w;
        }
    }

    float mreg[4], lreg[4], oacc[4][4];
#pragma unroll
    for (int i = 0; i < 4; ++i) {
        mreg[i] = -CUDART_INF_F; lreg[i] = 0.f;
#pragma unroll
        for (int j = 0; j < 4; ++j) oacc[i][j] = 0.f;
    }

    for (int kt = 0; kt < 32; ++kt) {
        __syncthreads();
        {
            const int tok = segBase + (kt * 64 + lr) * r;
            const float* kp = qkv + (size_t)tok * E3 + EDIM + h * HD;
            const float* vp = kp + EDIM;
#pragma unroll
            for (int ii = 0; ii < 4; ++ii) {
                const int d = ld + ii * 16;
                float4 kv = *(const float4*)(kp + d);
                KPst[d+0][lr] = kv.x; KPst[d+1][lr] = kv.y; KPst[d+2][lr] = kv.z; KPst[d+3][lr] = kv.w;
                *(float4*)&Vs[lr][d] = *(const float4*)(vp + d);
            }
        }
        __syncthreads();

        float sc[4][4];
#pragma unroll
        for (int i = 0; i < 4; ++i)
#pragma unroll
            for (int j = 0; j < 4; ++j) sc[i][j] = 0.f;
#pragma unroll 8
        for (int d = 0; d < 64; ++d) {
            float4 qa = *(const float4*)&Qst[d][ty * 4];
            float4 kb = *(const float4*)&KPst[d][tx * 4];
            float a[4] = {qa.x, qa.y, qa.z, qa.w};
            float b[4] = {kb.x, kb.y, kb.z, kb.w};
#pragma unroll
            for (int i = 0; i < 4; ++i)
#pragma unroll
                for (int j = 0; j < 4; ++j) sc[i][j] = fmaf(a[i], b[j], sc[i][j]);
        }
#pragma unroll
        for (int i = 0; i < 4; ++i)
#pragma unroll
            for (int j = 0; j < 4; ++j) sc[i][j] *= ATTN_SCALE;

#pragma unroll
        for (int i = 0; i < 4; ++i) {
            float tm = fmaxf(fmaxf(sc[i][0], sc[i][1]), fmaxf(sc[i][2], sc[i][3]));
#pragma unroll
            for (int w = 8; w >= 1; w >>= 1)
                tm = fmaxf(tm, __shfl_xor_sync(0xffffffffu, tm, w));
            float nm = fmaxf(mreg[i], tm);
            float corr = __expf(mreg[i] - nm);
            float rs = 0.f;
#pragma unroll
            for (int j = 0; j < 4; ++j) { sc[i][j] = __expf(sc[i][j] - nm); rs += sc[i][j]; }
#pragma unroll
            for (int w = 8; w >= 1; w >>= 1)
                rs += __shfl_xor_sync(0xffffffffu, rs, w);
            lreg[i] = lreg[i] * corr + rs;
            mreg[i] = nm;
#pragma unroll
            for (int j = 0; j < 4; ++j) oacc[i][j] *= corr;
        }

        __syncthreads();
#pragma unroll
        for (int i = 0; i < 4; ++i)
#pragma unroll
            for (int j = 0; j < 4; ++j)
                KPst[tx * 4 + j][ty * 4 + i] = sc[i][j];
        __syncthreads();

#pragma unroll 8
        for (int kk = 0; kk < 64; ++kk) {
            float4 pa = *(const float4*)&KPst[kk][ty * 4];
            float4 vb = *(const float4*)&Vs[kk][tx * 4];
            float a[4] = {pa.x, pa.y, pa.z, pa.w};
            float b[4] = {vb.x, vb.y, vb.z, vb.w};
#pragma unroll
            for (int i = 0; i < 4; ++i)
#pragma unroll
                for (int j = 0; j < 4; ++j) oacc[i][j] = fmaf(a[i], b[j], oacc[i][j]);
        }
    }

#pragma unroll
    for (int i = 0; i < 4; ++i) {
        const float inv = 1.f / lreg[i];
        const int tok = segBase + (blockIdx.x * 64 + ty * 4 + i) * r;
        *(float4*)(g_o + (size_t)tok * EDIM + h * HD + tx * 4) =
            make_float4(oacc[i][0] * inv, oacc[i][1] * inv,
                        oacc[i][2] * inv, oacc[i][3] * inv);
    }
}

// ---------------------------------------------------------------------------
// LayerNorm over 768; emits bf16 hi/lo directly for the tensor-core out-proj.
// ---------------------------------------------------------------------------
__global__ __launch_bounds__(256) void layernorm_k(
    const float* __restrict__ gamma, const float* __restrict__ beta)
{
    __shared__ float red[8];
    __shared__ float bcast;
    const int row = blockIdx.x;
    const int tid = threadIdx.x;
    const int lane = tid & 31, wid = tid >> 5;
    const float* x = g_o + (size_t)row * EDIM;
    float v0 = x[tid], v1 = x[tid + 256], v2 = x[tid + 512];

    float ssum = v0 + v1 + v2;
#pragma unroll
    for (int w = 16; w >= 1; w >>= 1) ssum += __shfl_xor_sync(0xffffffffu, ssum, w);
    if (lane == 0) red[wid] = ssum;
    __syncthreads();
    if (tid < 32) {
        float t = (tid < 8) ? red[tid] : 0.f;
#pragma unroll
        for (int w = 4; w >= 1; w >>= 1) t += __shfl_xor_sync(0xffffffffu, t, w);
        if (tid == 0) bcast = t;
    }
    __syncthreads();
    const float mu = bcast * (1.f / 768.f);
    float d0 = v0 - mu, d1 = v1 - mu, d2 = v2 - mu;
    float sq = d0 * d0 + d1 * d1 + d2 * d2;
#pragma unroll
    for (int w = 16; w >= 1; w >>= 1) sq += __shfl_xor_sync(0xffffffffu, sq, w);
    __syncthreads();
    if (lane == 0) red[wid] = sq;
    __syncthreads();
    if (tid < 32) {
        float t = (tid < 8) ? red[tid] : 0.f;
#pragma unroll
        for (int w = 4; w >= 1; w >>= 1) t += __shfl_xor_sync(0xffffffffu, t, w);
        if (tid == 0) bcast = t;
    }
    __syncthreads();
    const float rstd = rsqrtf(bcast * (1.f / 768.f) + 1e-5f);
    const size_t rb = (size_t)row * EDIM;
#pragma unroll
    for (int part = 0; part < 3; ++part) {
        const int idx = tid + part * 256;
        const float d = (part == 0) ? d0 : (part == 1) ? d1 : d2;
        const float y = d * rstd * gamma[idx] + beta[idx];
        __nv_bfloat16 h = __float2bfloat16_rn(y);
        g_onhi[rb + idx] = h;
        g_onlo[rb + idx] = __float2bfloat16_rn(y - __bfloat162float(h));
    }
}

__global__ void zero_o() {
    ((float4*)g_o)[blockIdx.x * blockDim.x + threadIdx.x] =
        make_float4(0.f, 0.f, 0.f, 0.f);
}

// ---------------------------------------------------------------------------
extern "C" void kernel_launch(void* const* d_in, const int* in_sizes, int n_in,
                              void* d_out, int out_size)
{
    const float* x      = (const float*)d_in[0];
    const float* w_qkv  = (const float*)d_in[1];
    const float* b_qkv  = (const float*)d_in[2];
    const float* w_out  = (const float*)d_in[3];
    const float* b_out  = (const float*)d_in[4];
    const float* ln_g   = (const float*)d_in[5];
    const float* ln_b   = (const float*)d_in[6];
    float* out = (float*)d_out;

    const int SMEM_GEMM = 2 * STG_B;   // 80 KB
    cudaFuncSetAttribute(wgemm<0>, cudaFuncAttributeMaxDynamicSharedMemorySize, SMEM_GEMM);
    cudaFuncSetAttribute(wgemm<1>, cudaFuncAttributeMaxDynamicSharedMemorySize, SMEM_GEMM);

    // split fp32 -> bf16 hi/lo
    split_k<0><<<(NTOK * EDIM / 4) / 256, 256>>>(x);
    split_k<1><<<(E3 * EDIM / 4) / 256, 256>>>(w_qkv);
    split_k<2><<<(EDIM * EDIM / 4) / 256, 256>>>(w_out);

    // QKV projection (tensor cores, split bf16)
    dim3 g1(E3 / 128, NTOK / 128);
    wgemm<0><<<g1, 256, SMEM_GEMM>>>(b_qkv, nullptr);

    zero_o<<<(NTOK * EDIM / 4) / 256, 256>>>();

    dim3 g2(32, 28);
    dilated_attn<<<g2, 256>>>();

    layernorm_k<<<NTOK, 256>>>(ln_g, ln_b);

    // out projection (tensor cores, split bf16)
    dim3 g3(EDIM / 128, NTOK / 128);
    wgemm<1><<<g3, 256, SMEM_GEMM>>>(b_out, out);
}